// round 2
// baseline (speedup 1.0000x reference)
#include <cuda_runtime.h>
#include <cuda_bf16.h>
#include <cstdint>
#include <cstddef>

// ---------------------------------------------------------------------------
// Problem dims (fixed)
// ---------------------------------------------------------------------------
#define BATCH   4
#define SEQ     2048
#define TOK     (BATCH * SEQ)      // 8192
#define DMODEL  384
#define INNER   768
#define STATE   16
#define KW      4
#define FFN     1024

// ---------------------------------------------------------------------------
// Scratch (device globals; no allocation allowed)
// ---------------------------------------------------------------------------
__device__ float g_h   [TOK * DMODEL];        // rms1 out
__device__ float g_xz  [TOK * 2 * INNER];     // in_proj out (x_inner | z)
__device__ float g_xs  [TOK * KW * INNER];    // im2col shifted input for conv
__device__ float g_xc  [TOK * INNER];         // conv out (silu)
__device__ float g_bc  [TOK * 2 * STATE];     // x_proj out (B | C)
__device__ float g_dl  [TOK * INNER];         // delta (pre-softplus)
__device__ float g_y   [TOK * INNER];         // gated scan output
__device__ float g_o   [TOK * DMODEL];        // out_proj result
__device__ float g_x2  [TOK * DMODEL];        // residual after mamba
__device__ float g_h2  [TOK * DMODEL];        // rms2 out
__device__ float g_gate[TOK * FFN];
__device__ float g_up  [TOK * FFN];
__device__ float g_hid [TOK * FFN];

// ---------------------------------------------------------------------------
// SGEMM: C[M,N] = A[M,K] @ B[K,N], row-major, 128x128x8 tiles, 8x8/thread
// mode: 0 = store, 1 = silu(acc+bias), 2 = acc+bias, 3 = acc + res[m*N+n]
// Requires K % 8 == 0, N % 4 == 0.
// ---------------------------------------------------------------------------
#define BM 128
#define BN 128
#define BK 8
#define TM 8
#define TN 8

__global__ __launch_bounds__(256) void sgemm_kernel(
    const float* __restrict__ A, const float* __restrict__ B,
    float* __restrict__ C, int M, int N, int K,
    int mode, const float* __restrict__ bias, const float* __restrict__ res)
{
    __shared__ float As[BK][BM];
    __shared__ float Bs[BK][BN];

    const int tid = threadIdx.x;
    const int m0 = blockIdx.y * BM;
    const int n0 = blockIdx.x * BN;

    const int a_row = tid >> 1;          // 0..127
    const int a_col = (tid & 1) * 4;     // 0 or 4
    const int b_row = tid >> 5;          // 0..7
    const int b_col = (tid & 31) * 4;    // 0..124

    const int ty = tid >> 4;             // 0..15
    const int tx = tid & 15;             // 0..15

    float acc[TM][TN];
    #pragma unroll
    for (int i = 0; i < TM; i++)
        #pragma unroll
        for (int j = 0; j < TN; j++) acc[i][j] = 0.f;

    const float* Aptr = A + (size_t)m0 * K;

    for (int k0 = 0; k0 < K; k0 += BK) {
        float4 av = make_float4(0.f, 0.f, 0.f, 0.f);
        if (m0 + a_row < M)
            av = *(const float4*)(Aptr + (size_t)a_row * K + k0 + a_col);
        As[a_col + 0][a_row] = av.x;
        As[a_col + 1][a_row] = av.y;
        As[a_col + 2][a_row] = av.z;
        As[a_col + 3][a_row] = av.w;

        float4 bv = make_float4(0.f, 0.f, 0.f, 0.f);
        if (n0 + b_col + 3 < N)          // N%4==0 -> float4 fully in or out
            bv = *(const float4*)(B + (size_t)(k0 + b_row) * N + n0 + b_col);
        *(float4*)&Bs[b_row][b_col] = bv;

        __syncthreads();

        #pragma unroll
        for (int kk = 0; kk < BK; kk++) {
            float a_frag[TM], b_frag[TN];
            #pragma unroll
            for (int i = 0; i < TM; i++) a_frag[i] = As[kk][ty * TM + i];
            #pragma unroll
            for (int j = 0; j < TN; j++) b_frag[j] = Bs[kk][tx * TN + j];
            #pragma unroll
            for (int i = 0; i < TM; i++)
                #pragma unroll
                for (int j = 0; j < TN; j++)
                    acc[i][j] += a_frag[i] * b_frag[j];
        }
        __syncthreads();
    }

    #pragma unroll
    for (int i = 0; i < TM; i++) {
        const int m = m0 + ty * TM + i;
        if (m >= M) continue;
        #pragma unroll
        for (int j = 0; j < TN; j++) {
            const int n = n0 + tx * TN + j;
            if (n >= N) continue;
            float v = acc[i][j];
            if (mode == 1)      { v += bias[n]; v = v / (1.f + __expf(-v)); }
            else if (mode == 2) { v += bias[n]; }
            else if (mode == 3) { v += res[(size_t)m * N + n]; }
            C[(size_t)m * N + n] = v;
        }
    }
}

// ---------------------------------------------------------------------------
// RMSNorm (warp per token, D=384 -> 12 elems/lane)
// ---------------------------------------------------------------------------
__global__ void rmsnorm_kernel(const float* __restrict__ x,
                               const float* __restrict__ w,
                               float* __restrict__ out)
{
    const int warp = (blockIdx.x * blockDim.x + threadIdx.x) >> 5;
    const int lane = threadIdx.x & 31;
    if (warp >= TOK) return;
    const float* row = x + (size_t)warp * DMODEL;
    float ss = 0.f;
    float v[12];
    #pragma unroll
    for (int c = 0; c < 12; c++) {
        v[c] = row[lane + c * 32];
        ss += v[c] * v[c];
    }
    #pragma unroll
    for (int o = 16; o; o >>= 1) ss += __shfl_xor_sync(0xffffffffu, ss, o);
    const float inv = rsqrtf(ss * (1.f / DMODEL) + 1e-6f);
    float* orow = out + (size_t)warp * DMODEL;
    #pragma unroll
    for (int c = 0; c < 12; c++) {
        const int i = lane + c * 32;
        orow[i] = v[c] * inv * w[i];
    }
}

// ---------------------------------------------------------------------------
// im2col for conv: xs[tok, w*INNER + i] = x_inner[b, t-1+w, i] (0 outside seq)
// x_inner = first INNER cols of g_xz (row stride 2*INNER). float4 grain.
// ---------------------------------------------------------------------------
__global__ void conv_shift_kernel(const float* __restrict__ xz,
                                  float* __restrict__ xs)
{
    const int idx = blockIdx.x * blockDim.x + threadIdx.x;   // float4 id
    const int total = TOK * KW * INNER / 4;
    if (idx >= total) return;
    const int e = idx * 4;
    const int tok = e / (KW * INNER);
    const int c = e - tok * (KW * INNER);
    const int w = c / INNER;
    const int i = c - w * INNER;
    const int b = tok >> 11;
    const int t = tok & (SEQ - 1);
    const int ts = t - 1 + w;
    float4 v = make_float4(0.f, 0.f, 0.f, 0.f);
    if (ts >= 0 && ts < SEQ)
        v = *(const float4*)(xz + ((size_t)(b * SEQ + ts)) * (2 * INNER) + i);
    *(float4*)(xs + (size_t)e) = v;
}

// ---------------------------------------------------------------------------
// Selective scan. One thread per (b, d, n); 16 lanes per (b, d) group.
// Fused epilogue: y = (scan + D*x) * silu(z)
// ---------------------------------------------------------------------------
__global__ void scan_kernel(const float* __restrict__ xc,
                            const float* __restrict__ delta,
                            const float* __restrict__ bc,
                            const float* __restrict__ A_log,
                            const float* __restrict__ Dp,
                            const float* __restrict__ xz,
                            float* __restrict__ y)
{
    const int tid = blockIdx.x * blockDim.x + threadIdx.x;
    const int gid = tid >> 4;
    const int n = tid & 15;
    if (gid >= BATCH * INNER) return;
    const int b = gid / INNER;
    const int d = gid - b * INNER;

    const float A = -__expf(A_log[d * STATE + n]);
    const float Dv = Dp[d];
    float h = 0.f;
    const size_t base = (size_t)b * SEQ;

    for (int t = 0; t < SEQ; t++) {
        const size_t tok = base + t;
        const float dlt = delta[tok * INNER + d];
        const float xv  = xc[tok * INNER + d];
        const float Bv  = bc[tok * 2 * STATE + n];
        const float Cv  = bc[tok * 2 * STATE + STATE + n];
        const float dsp = (dlt > 20.f) ? dlt : log1pf(__expf(dlt));
        h = __expf(dsp * A) * h + dsp * Bv * xv;
        float p = h * Cv;
        p += __shfl_xor_sync(0xffffffffu, p, 8);
        p += __shfl_xor_sync(0xffffffffu, p, 4);
        p += __shfl_xor_sync(0xffffffffu, p, 2);
        p += __shfl_xor_sync(0xffffffffu, p, 1);
        if (n == 0) {
            const float zv = xz[tok * 2 * INNER + INNER + d];
            const float sz = zv / (1.f + __expf(-zv));
            y[tok * INNER + d] = (p + Dv * xv) * sz;
        }
    }
}

// ---------------------------------------------------------------------------
// Fused: x2 = xres + LayerNorm(o)*gamma+beta ; h2 = RMSNorm(x2)*rms_w
// warp per token.
// ---------------------------------------------------------------------------
__global__ void ln_residual_rms_kernel(const float* __restrict__ o_,
                                       const float* __restrict__ xres,
                                       const float* __restrict__ gamma,
                                       const float* __restrict__ beta,
                                       const float* __restrict__ rms_w,
                                       float* __restrict__ x2,
                                       float* __restrict__ h2)
{
    const int warp = (blockIdx.x * blockDim.x + threadIdx.x) >> 5;
    const int lane = threadIdx.x & 31;
    if (warp >= TOK) return;
    const size_t row = (size_t)warp * DMODEL;

    float o[12];
    float mu = 0.f;
    #pragma unroll
    for (int c = 0; c < 12; c++) {
        o[c] = o_[row + lane + c * 32];
        mu += o[c];
    }
    #pragma unroll
    for (int s = 16; s; s >>= 1) mu += __shfl_xor_sync(0xffffffffu, mu, s);
    mu *= (1.f / DMODEL);

    float var = 0.f;
    #pragma unroll
    for (int c = 0; c < 12; c++) {
        const float dd = o[c] - mu;
        var += dd * dd;
    }
    #pragma unroll
    for (int s = 16; s; s >>= 1) var += __shfl_xor_sync(0xffffffffu, var, s);
    var *= (1.f / DMODEL);
    const float inv = rsqrtf(var + 1e-5f);

    float r[12];
    float ss = 0.f;
    #pragma unroll
    for (int c = 0; c < 12; c++) {
        const int i = lane + c * 32;
        const float v = xres[row + i] + (o[c] - mu) * inv * gamma[i] + beta[i];
        r[c] = v;
        x2[row + i] = v;
        ss += v * v;
    }
    #pragma unroll
    for (int s = 16; s; s >>= 1) ss += __shfl_xor_sync(0xffffffffu, ss, s);
    const float rinv = rsqrtf(ss * (1.f / DMODEL) + 1e-6f);
    #pragma unroll
    for (int c = 0; c < 12; c++) {
        const int i = lane + c * 32;
        h2[row + i] = r[c] * rinv * rms_w[i];
    }
}

// ---------------------------------------------------------------------------
// hidden = silu(gate) * up
// ---------------------------------------------------------------------------
__global__ void silumul_kernel(const float* __restrict__ g,
                               const float* __restrict__ u,
                               float* __restrict__ out, int n)
{
    const int i = blockIdx.x * blockDim.x + threadIdx.x;
    if (i >= n) return;
    const float gv = g[i];
    out[i] = (gv / (1.f + __expf(-gv))) * u[i];
}

// ---------------------------------------------------------------------------
// launch
// ---------------------------------------------------------------------------
static inline float* sym(const void* symbol)
{
    void* p = nullptr;
    cudaGetSymbolAddress(&p, symbol);
    return (float*)p;
}

extern "C" void kernel_launch(void* const* d_in, const int* in_sizes, int n_in,
                              void* d_out, int out_size)
{
    const float* x        = (const float*)d_in[0];
    const float* rms1_w   = (const float*)d_in[1];
    const float* rms2_w   = (const float*)d_in[2];
    const float* in_proj  = (const float*)d_in[3];
    const float* conv_w   = (const float*)d_in[4];
    const float* conv_b   = (const float*)d_in[5];
    const float* x_proj   = (const float*)d_in[6];
    const float* dt_proj  = (const float*)d_in[7];
    const float* dt_b     = (const float*)d_in[8];
    const float* A_log    = (const float*)d_in[9];
    const float* D_param  = (const float*)d_in[10];
    const float* out_proj = (const float*)d_in[11];
    const float* ln_g     = (const float*)d_in[12];
    const float* ln_b     = (const float*)d_in[13];
    const float* gate_w   = (const float*)d_in[14];
    const float* up_w     = (const float*)d_in[15];
    const float* down_w   = (const float*)d_in[16];
    float* out = (float*)d_out;

    float* h    = sym(g_h);
    float* xz   = sym(g_xz);
    float* xs   = sym(g_xs);
    float* xc   = sym(g_xc);
    float* bc   = sym(g_bc);
    float* dl   = sym(g_dl);
    float* y    = sym(g_y);
    float* o    = sym(g_o);
    float* x2   = sym(g_x2);
    float* h2   = sym(g_h2);
    float* gate = sym(g_gate);
    float* up   = sym(g_up);
    float* hid  = sym(g_hid);

    const dim3 tpb(256);

    // 1. h = rmsnorm(x) * rms1_w
    rmsnorm_kernel<<<TOK / 8, 256>>>(x, rms1_w, h);

    // 2. xz = h @ in_proj_w   [8192,1536]
    sgemm_kernel<<<dim3((2 * INNER) / BN, TOK / BM), tpb>>>(
        h, in_proj, xz, TOK, 2 * INNER, DMODEL, 0, nullptr, nullptr);

    // 3. im2col shift
    {
        const int total = TOK * KW * INNER / 4;
        conv_shift_kernel<<<(total + 255) / 256, tpb>>>(xz, xs);
    }

    // 4. xc = silu(xs @ conv_w_reshaped + conv_b)   K=3072
    sgemm_kernel<<<dim3(INNER / BN, TOK / BM), tpb>>>(
        xs, conv_w, xc, TOK, INNER, KW * INNER, 1, conv_b, nullptr);

    // 5. bc = xc @ x_proj_w   [8192,32]
    sgemm_kernel<<<dim3(1, TOK / BM), tpb>>>(
        xc, x_proj, bc, TOK, 2 * STATE, INNER, 0, nullptr, nullptr);

    // 6. dl = xc @ dt_proj_w + dt_b
    sgemm_kernel<<<dim3(INNER / BN, TOK / BM), tpb>>>(
        xc, dt_proj, dl, TOK, INNER, INNER, 2, dt_b, nullptr);

    // 7. selective scan + gating
    scan_kernel<<<(BATCH * INNER * STATE) / 256, tpb>>>(
        xc, dl, bc, A_log, D_param, xz, y);

    // 8. o = y @ out_proj_w   [8192,384]
    sgemm_kernel<<<dim3(DMODEL / BN + (DMODEL % BN ? 1 : 0), TOK / BM), tpb>>>(
        y, out_proj, o, TOK, DMODEL, INNER, 0, nullptr, nullptr);

    // 9. x2 = x + LN(o); h2 = RMSNorm(x2)
    ln_residual_rms_kernel<<<TOK / 8, 256>>>(o, x, ln_g, ln_b, rms2_w, x2, h2);

    // 10/11. gate, up GEMMs
    sgemm_kernel<<<dim3(FFN / BN, TOK / BM), tpb>>>(
        h2, gate_w, gate, TOK, FFN, DMODEL, 0, nullptr, nullptr);
    sgemm_kernel<<<dim3(FFN / BN, TOK / BM), tpb>>>(
        h2, up_w, up, TOK, FFN, DMODEL, 0, nullptr, nullptr);

    // 12. hid = silu(gate) * up
    silumul_kernel<<<(TOK * FFN + 255) / 256, tpb>>>(gate, up, hid, TOK * FFN);

    // 13. out = x2 + hid @ down_w
    sgemm_kernel<<<dim3(DMODEL / BN + (DMODEL % BN ? 1 : 0), TOK / BM), tpb>>>(
        hid, down_w, out, TOK, DMODEL, FFN, 3, nullptr, x2);
}

// round 4
// speedup vs baseline: 1.5410x; 1.5410x over previous
#include <cuda_runtime.h>
#include <cuda_bf16.h>
#include <cstdint>
#include <cstddef>

// ---------------------------------------------------------------------------
// Problem dims (fixed)
// ---------------------------------------------------------------------------
#define BATCH   4
#define SEQ     2048
#define TOK     (BATCH * SEQ)      // 8192
#define DMODEL  384
#define INNER   768
#define STATE   16
#define KW      4
#define FFN     1024

// ---------------------------------------------------------------------------
// Scratch (device globals; no allocation allowed)
// ---------------------------------------------------------------------------
__device__ float g_h   [TOK * DMODEL];        // rms1 out
__device__ float g_xz  [TOK * 2 * INNER];     // in_proj out (x_inner | z)
__device__ float g_xs  [TOK * KW * INNER];    // im2col shifted input for conv
__device__ float g_xc  [TOK * INNER];         // conv out (silu)
__device__ float g_bc  [TOK * 2 * STATE];     // x_proj out (B | C)
__device__ float g_dl  [TOK * INNER];         // delta (pre-softplus)
__device__ float g_y   [TOK * INNER];         // gated scan output
__device__ float g_o   [TOK * DMODEL];        // out_proj result
__device__ float g_x2  [TOK * DMODEL];        // residual after mamba
__device__ float g_h2  [TOK * DMODEL];        // rms2 out
__device__ float g_gate[TOK * FFN];
__device__ float g_up  [TOK * FFN];
__device__ float g_hid [TOK * FFN];

// ---------------------------------------------------------------------------
// TF32 tensor-core GEMM: C[M,N] = A[M,K] @ B[K,N], row-major.
// CTA tile 128x128, BK=16 double-buffered, 8 warps each 32(M)x64(N),
// mma.sync.aligned.m16n8k8.row.col.f32.tf32.tf32.f32
// Requirements: M % 128 == 0, K % 16 == 0, N % 4 == 0 (guards on N only).
// mode: 0 = store, 1 = silu(acc+bias), 2 = acc+bias, 3 = acc + res[m*N+n]
// ---------------------------------------------------------------------------
#define BM 128
#define BN 128
#define BKT 16
#define LDA (BM + 4)
#define LDB (BN + 4)

__device__ __forceinline__ uint32_t f2tf(float f)
{
    uint32_t u;
    asm("cvt.rna.tf32.f32 %0, %1;" : "=r"(u) : "f"(f));
    return u;
}

__device__ __forceinline__ void mma_tf32(float c[4], const uint32_t a[4],
                                         const uint32_t b[2])
{
    asm volatile(
        "mma.sync.aligned.m16n8k8.row.col.f32.tf32.tf32.f32 "
        "{%0,%1,%2,%3}, {%4,%5,%6,%7}, {%8,%9}, {%0,%1,%2,%3};\n"
        : "+f"(c[0]), "+f"(c[1]), "+f"(c[2]), "+f"(c[3])
        : "r"(a[0]), "r"(a[1]), "r"(a[2]), "r"(a[3]),
          "r"(b[0]), "r"(b[1]));
}

__global__ __launch_bounds__(256, 2) void mma_gemm_kernel(
    const float* __restrict__ A, const float* __restrict__ B,
    float* __restrict__ C, int M, int N, int K,
    int mode, const float* __restrict__ bias, const float* __restrict__ res)
{
    __shared__ uint32_t As[2][BKT][LDA];
    __shared__ uint32_t Bs[2][BKT][LDB];

    const int tid  = threadIdx.x;
    const int wid  = tid >> 5;
    const int lane = tid & 31;
    const int g    = lane >> 2;   // 0..7
    const int tig  = lane & 3;    // 0..3

    const int warpM = (wid & 3) * 32;
    const int warpN = (wid >> 2) * 64;

    const int m0 = blockIdx.y * BM;
    const int n0 = blockIdx.x * BN;

    // global->smem load mapping
    const int ar = tid >> 2;          // 0..63  (rows ar, ar+64)
    const int ac = (tid & 3) * 4;     // 0,4,8,12
    const int br = tid >> 5;          // 0..7   (rows br, br+8)
    const int bcn = (tid & 31) * 4;   // 0..124

    float acc[2][8][4];
    #pragma unroll
    for (int mt = 0; mt < 2; mt++)
        #pragma unroll
        for (int nt = 0; nt < 8; nt++)
            #pragma unroll
            for (int r = 0; r < 4; r++) acc[mt][nt][r] = 0.f;

    const bool bok = (n0 + bcn + 3) < N;   // N % 4 == 0 -> whole float4 in/out
    const float4 zero4 = make_float4(0.f, 0.f, 0.f, 0.f);

    const float* Ab = A + (size_t)(m0 + ar) * K + ac;
    const float* Bb = B + (size_t)br * N + n0 + bcn;

    float4 av0, av1, bv0, bv1;

    // prologue: load tile 0
    av0 = *(const float4*)(Ab);
    av1 = *(const float4*)(Ab + (size_t)64 * K);
    bv0 = bok ? *(const float4*)(Bb) : zero4;
    bv1 = bok ? *(const float4*)(Bb + (size_t)8 * N) : zero4;

    const int ntiles = K / BKT;
    int buf = 0;

    // store tile 0
    {
        As[0][ac + 0][ar] = f2tf(av0.x);
        As[0][ac + 1][ar] = f2tf(av0.y);
        As[0][ac + 2][ar] = f2tf(av0.z);
        As[0][ac + 3][ar] = f2tf(av0.w);
        As[0][ac + 0][ar + 64] = f2tf(av1.x);
        As[0][ac + 1][ar + 64] = f2tf(av1.y);
        As[0][ac + 2][ar + 64] = f2tf(av1.z);
        As[0][ac + 3][ar + 64] = f2tf(av1.w);
        Bs[0][br][bcn + 0] = f2tf(bv0.x);
        Bs[0][br][bcn + 1] = f2tf(bv0.y);
        Bs[0][br][bcn + 2] = f2tf(bv0.z);
        Bs[0][br][bcn + 3] = f2tf(bv0.w);
        Bs[0][br + 8][bcn + 0] = f2tf(bv1.x);
        Bs[0][br + 8][bcn + 1] = f2tf(bv1.y);
        Bs[0][br + 8][bcn + 2] = f2tf(bv1.z);
        Bs[0][br + 8][bcn + 3] = f2tf(bv1.w);
    }
    __syncthreads();

    for (int t = 0; t < ntiles; t++) {
        // prefetch next tile into registers
        if (t + 1 < ntiles) {
            const int k0 = (t + 1) * BKT;
            av0 = *(const float4*)(Ab + k0);
            av1 = *(const float4*)(Ab + k0 + (size_t)64 * K);
            bv0 = bok ? *(const float4*)(Bb + (size_t)k0 * N) : zero4;
            bv1 = bok ? *(const float4*)(Bb + (size_t)(k0 + 8) * N) : zero4;
        }

        // compute on current buffer: 2 k-steps of 8
        #pragma unroll
        for (int ks = 0; ks < BKT; ks += 8) {
            uint32_t afr[2][4];
            #pragma unroll
            for (int mt = 0; mt < 2; mt++) {
                const int mb = warpM + mt * 16;
                afr[mt][0] = As[buf][ks + tig    ][mb + g];
                afr[mt][1] = As[buf][ks + tig    ][mb + g + 8];
                afr[mt][2] = As[buf][ks + tig + 4][mb + g];
                afr[mt][3] = As[buf][ks + tig + 4][mb + g + 8];
            }
            uint32_t bfr[8][2];
            #pragma unroll
            for (int nt = 0; nt < 8; nt++) {
                const int nb = warpN + nt * 8;
                bfr[nt][0] = Bs[buf][ks + tig    ][nb + g];
                bfr[nt][1] = Bs[buf][ks + tig + 4][nb + g];
            }
            #pragma unroll
            for (int mt = 0; mt < 2; mt++)
                #pragma unroll
                for (int nt = 0; nt < 8; nt++)
                    mma_tf32(acc[mt][nt], afr[mt], bfr[nt]);
        }

        // stage next tile to the other buffer
        if (t + 1 < ntiles) {
            const int nb = buf ^ 1;
            As[nb][ac + 0][ar] = f2tf(av0.x);
            As[nb][ac + 1][ar] = f2tf(av0.y);
            As[nb][ac + 2][ar] = f2tf(av0.z);
            As[nb][ac + 3][ar] = f2tf(av0.w);
            As[nb][ac + 0][ar + 64] = f2tf(av1.x);
            As[nb][ac + 1][ar + 64] = f2tf(av1.y);
            As[nb][ac + 2][ar + 64] = f2tf(av1.z);
            As[nb][ac + 3][ar + 64] = f2tf(av1.w);
            Bs[nb][br][bcn + 0] = f2tf(bv0.x);
            Bs[nb][br][bcn + 1] = f2tf(bv0.y);
            Bs[nb][br][bcn + 2] = f2tf(bv0.z);
            Bs[nb][br][bcn + 3] = f2tf(bv0.w);
            Bs[nb][br + 8][bcn + 0] = f2tf(bv1.x);
            Bs[nb][br + 8][bcn + 1] = f2tf(bv1.y);
            Bs[nb][br + 8][bcn + 2] = f2tf(bv1.z);
            Bs[nb][br + 8][bcn + 3] = f2tf(bv1.w);
            __syncthreads();
            buf = nb;
        }
    }

    // epilogue
    #pragma unroll
    for (int mt = 0; mt < 2; mt++) {
        #pragma unroll
        for (int nt = 0; nt < 8; nt++) {
            const int mA = m0 + warpM + mt * 16 + g;
            const int mB = mA + 8;
            const int n  = n0 + warpN + nt * 8 + tig * 2;
            #pragma unroll
            for (int half = 0; half < 2; half++) {
                const int m = half ? mB : mA;
                float v0 = half ? acc[mt][nt][2] : acc[mt][nt][0];
                float v1 = half ? acc[mt][nt][3] : acc[mt][nt][1];
                if (mode == 1) {
                    if (n < N)     { v0 += bias[n];     v0 = v0 / (1.f + __expf(-v0)); }
                    if (n + 1 < N) { v1 += bias[n + 1]; v1 = v1 / (1.f + __expf(-v1)); }
                } else if (mode == 2) {
                    if (n < N)     v0 += bias[n];
                    if (n + 1 < N) v1 += bias[n + 1];
                } else if (mode == 3) {
                    if (n < N)     v0 += res[(size_t)m * N + n];
                    if (n + 1 < N) v1 += res[(size_t)m * N + n + 1];
                }
                if (n < N)     C[(size_t)m * N + n]     = v0;
                if (n + 1 < N) C[(size_t)m * N + n + 1] = v1;
            }
        }
    }
}

// ---------------------------------------------------------------------------
// RMSNorm (warp per token, D=384 -> 12 elems/lane)
// ---------------------------------------------------------------------------
__global__ void rmsnorm_kernel(const float* __restrict__ x,
                               const float* __restrict__ w,
                               float* __restrict__ out)
{
    const int warp = (blockIdx.x * blockDim.x + threadIdx.x) >> 5;
    const int lane = threadIdx.x & 31;
    if (warp >= TOK) return;
    const float* row = x + (size_t)warp * DMODEL;
    float ss = 0.f;
    float v[12];
    #pragma unroll
    for (int c = 0; c < 12; c++) {
        v[c] = row[lane + c * 32];
        ss += v[c] * v[c];
    }
    #pragma unroll
    for (int o = 16; o; o >>= 1) ss += __shfl_xor_sync(0xffffffffu, ss, o);
    const float inv = rsqrtf(ss * (1.f / DMODEL) + 1e-6f);
    float* orow = out + (size_t)warp * DMODEL;
    #pragma unroll
    for (int c = 0; c < 12; c++) {
        const int i = lane + c * 32;
        orow[i] = v[c] * inv * w[i];
    }
}

// ---------------------------------------------------------------------------
// im2col for conv: xs[tok, w*INNER + i] = x_inner[b, t-1+w, i] (0 outside seq)
// ---------------------------------------------------------------------------
__global__ void conv_shift_kernel(const float* __restrict__ xz,
                                  float* __restrict__ xs)
{
    const int idx = blockIdx.x * blockDim.x + threadIdx.x;   // float4 id
    const int total = TOK * KW * INNER / 4;
    if (idx >= total) return;
    const int e = idx * 4;
    const int tok = e / (KW * INNER);
    const int c = e - tok * (KW * INNER);
    const int w = c / INNER;
    const int i = c - w * INNER;
    const int b = tok >> 11;
    const int t = tok & (SEQ - 1);
    const int ts = t - 1 + w;
    float4 v = make_float4(0.f, 0.f, 0.f, 0.f);
    if (ts >= 0 && ts < SEQ)
        v = *(const float4*)(xz + ((size_t)(b * SEQ + ts)) * (2 * INNER) + i);
    *(float4*)(xs + (size_t)e) = v;
}

// ---------------------------------------------------------------------------
// Selective scan. One thread per (b, d, n); 16 lanes per (b, d) group.
// Fused epilogue: y = (scan + D*x) * silu(z)
// ---------------------------------------------------------------------------
__global__ void scan_kernel(const float* __restrict__ xc,
                            const float* __restrict__ delta,
                            const float* __restrict__ bc,
                            const float* __restrict__ A_log,
                            const float* __restrict__ Dp,
                            const float* __restrict__ xz,
                            float* __restrict__ y)
{
    const int tid = blockIdx.x * blockDim.x + threadIdx.x;
    const int gid = tid >> 4;
    const int n = tid & 15;
    if (gid >= BATCH * INNER) return;
    const int b = gid / INNER;
    const int d = gid - b * INNER;

    const float A = -__expf(A_log[d * STATE + n]);
    const float Dv = Dp[d];
    float h = 0.f;
    const size_t base = (size_t)b * SEQ;

    for (int t = 0; t < SEQ; t++) {
        const size_t tok = base + t;
        const float dlt = delta[tok * INNER + d];
        const float xv  = xc[tok * INNER + d];
        const float Bv  = bc[tok * 2 * STATE + n];
        const float Cv  = bc[tok * 2 * STATE + STATE + n];
        const float dsp = (dlt > 20.f) ? dlt : log1pf(__expf(dlt));
        h = __expf(dsp * A) * h + dsp * Bv * xv;
        float p = h * Cv;
        p += __shfl_xor_sync(0xffffffffu, p, 8);
        p += __shfl_xor_sync(0xffffffffu, p, 4);
        p += __shfl_xor_sync(0xffffffffu, p, 2);
        p += __shfl_xor_sync(0xffffffffu, p, 1);
        if (n == 0) {
            const float zv = xz[tok * 2 * INNER + INNER + d];
            const float sz = zv / (1.f + __expf(-zv));
            y[tok * INNER + d] = (p + Dv * xv) * sz;
        }
    }
}

// ---------------------------------------------------------------------------
// Fused: x2 = xres + LayerNorm(o)*gamma+beta ; h2 = RMSNorm(x2)*rms_w
// ---------------------------------------------------------------------------
__global__ void ln_residual_rms_kernel(const float* __restrict__ o_,
                                       const float* __restrict__ xres,
                                       const float* __restrict__ gamma,
                                       const float* __restrict__ beta,
                                       const float* __restrict__ rms_w,
                                       float* __restrict__ x2,
                                       float* __restrict__ h2)
{
    const int warp = (blockIdx.x * blockDim.x + threadIdx.x) >> 5;
    const int lane = threadIdx.x & 31;
    if (warp >= TOK) return;
    const size_t row = (size_t)warp * DMODEL;

    float o[12];
    float mu = 0.f;
    #pragma unroll
    for (int c = 0; c < 12; c++) {
        o[c] = o_[row + lane + c * 32];
        mu += o[c];
    }
    #pragma unroll
    for (int s = 16; s; s >>= 1) mu += __shfl_xor_sync(0xffffffffu, mu, s);
    mu *= (1.f / DMODEL);

    float var = 0.f;
    #pragma unroll
    for (int c = 0; c < 12; c++) {
        const float dd = o[c] - mu;
        var += dd * dd;
    }
    #pragma unroll
    for (int s = 16; s; s >>= 1) var += __shfl_xor_sync(0xffffffffu, var, s);
    var *= (1.f / DMODEL);
    const float inv = rsqrtf(var + 1e-5f);

    float r[12];
    float ss = 0.f;
    #pragma unroll
    for (int c = 0; c < 12; c++) {
        const int i = lane + c * 32;
        const float v = xres[row + i] + (o[c] - mu) * inv * gamma[i] + beta[i];
        r[c] = v;
        x2[row + i] = v;
        ss += v * v;
    }
    #pragma unroll
    for (int s = 16; s; s >>= 1) ss += __shfl_xor_sync(0xffffffffu, ss, s);
    const float rinv = rsqrtf(ss * (1.f / DMODEL) + 1e-6f);
    #pragma unroll
    for (int c = 0; c < 12; c++) {
        const int i = lane + c * 32;
        h2[row + i] = r[c] * rinv * rms_w[i];
    }
}

// ---------------------------------------------------------------------------
// hidden = silu(gate) * up
// ---------------------------------------------------------------------------
__global__ void silumul_kernel(const float* __restrict__ g,
                               const float* __restrict__ u,
                               float* __restrict__ out, int n)
{
    const int i = blockIdx.x * blockDim.x + threadIdx.x;
    if (i >= n) return;
    const float gv = g[i];
    out[i] = (gv / (1.f + __expf(-gv))) * u[i];
}

// ---------------------------------------------------------------------------
// launch
// ---------------------------------------------------------------------------
static inline float* sym(const void* symbol)
{
    void* p = nullptr;
    cudaGetSymbolAddress(&p, symbol);
    return (float*)p;
}

extern "C" void kernel_launch(void* const* d_in, const int* in_sizes, int n_in,
                              void* d_out, int out_size)
{
    const float* x        = (const float*)d_in[0];
    const float* rms1_w   = (const float*)d_in[1];
    const float* rms2_w   = (const float*)d_in[2];
    const float* in_proj  = (const float*)d_in[3];
    const float* conv_w   = (const float*)d_in[4];
    const float* conv_b   = (const float*)d_in[5];
    const float* x_proj   = (const float*)d_in[6];
    const float* dt_proj  = (const float*)d_in[7];
    const float* dt_b     = (const float*)d_in[8];
    const float* A_log    = (const float*)d_in[9];
    const float* D_param  = (const float*)d_in[10];
    const float* out_proj = (const float*)d_in[11];
    const float* ln_g     = (const float*)d_in[12];
    const float* ln_b     = (const float*)d_in[13];
    const float* gate_w   = (const float*)d_in[14];
    const float* up_w     = (const float*)d_in[15];
    const float* down_w   = (const float*)d_in[16];
    float* out = (float*)d_out;

    float* h    = sym(g_h);
    float* xz   = sym(g_xz);
    float* xs   = sym(g_xs);
    float* xc   = sym(g_xc);
    float* bc   = sym(g_bc);
    float* dl   = sym(g_dl);
    float* y    = sym(g_y);
    float* o    = sym(g_o);
    float* x2   = sym(g_x2);
    float* h2   = sym(g_h2);
    float* gate = sym(g_gate);
    float* up   = sym(g_up);
    float* hid  = sym(g_hid);

    const dim3 tpb(256);

    // 1. h = rmsnorm(x) * rms1_w
    rmsnorm_kernel<<<TOK / 8, 256>>>(x, rms1_w, h);

    // 2. xz = h @ in_proj_w   [8192,1536] K=384
    mma_gemm_kernel<<<dim3((2 * INNER) / BN, TOK / BM), tpb>>>(
        h, in_proj, xz, TOK, 2 * INNER, DMODEL, 0, nullptr, nullptr);

    // 3. im2col shift
    {
        const int total = TOK * KW * INNER / 4;
        conv_shift_kernel<<<(total + 255) / 256, tpb>>>(xz, xs);
    }

    // 4. xc = silu(xs @ conv_w_reshaped + conv_b)   K=3072
    mma_gemm_kernel<<<dim3(INNER / BN, TOK / BM), tpb>>>(
        xs, conv_w, xc, TOK, INNER, KW * INNER, 1, conv_b, nullptr);

    // 5. bc = xc @ x_proj_w   [8192,32]  K=768
    mma_gemm_kernel<<<dim3(1, TOK / BM), tpb>>>(
        xc, x_proj, bc, TOK, 2 * STATE, INNER, 0, nullptr, nullptr);

    // 6. dl = xc @ dt_proj_w + dt_b   K=768
    mma_gemm_kernel<<<dim3(INNER / BN, TOK / BM), tpb>>>(
        xc, dt_proj, dl, TOK, INNER, INNER, 2, dt_b, nullptr);

    // 7. selective scan + gating
    scan_kernel<<<(BATCH * INNER * STATE) / 256, tpb>>>(
        xc, dl, bc, A_log, D_param, xz, y);

    // 8. o = y @ out_proj_w   [8192,384] K=768
    mma_gemm_kernel<<<dim3(DMODEL / BN, TOK / BM), tpb>>>(
        y, out_proj, o, TOK, DMODEL, INNER, 0, nullptr, nullptr);

    // 9. x2 = x + LN(o); h2 = RMSNorm(x2)
    ln_residual_rms_kernel<<<TOK / 8, 256>>>(o, x, ln_g, ln_b, rms2_w, x2, h2);

    // 10/11. gate, up GEMMs  K=384
    mma_gemm_kernel<<<dim3(FFN / BN, TOK / BM), tpb>>>(
        h2, gate_w, gate, TOK, FFN, DMODEL, 0, nullptr, nullptr);
    mma_gemm_kernel<<<dim3(FFN / BN, TOK / BM), tpb>>>(
        h2, up_w, up, TOK, FFN, DMODEL, 0, nullptr, nullptr);

    // 12. hid = silu(gate) * up
    silumul_kernel<<<(TOK * FFN + 255) / 256, tpb>>>(gate, up, hid, TOK * FFN);

    // 13. out = x2 + hid @ down_w   K=1024
    mma_gemm_kernel<<<dim3(DMODEL / BN, TOK / BM), tpb>>>(
        hid, down_w, out, TOK, DMODEL, FFN, 3, nullptr, x2);
}

// round 6
// speedup vs baseline: 2.9676x; 1.9258x over previous
#include <cuda_runtime.h>
#include <cuda_bf16.h>
#include <cstdint>
#include <cstddef>

// ---------------------------------------------------------------------------
// Problem dims (fixed)
// ---------------------------------------------------------------------------
#define BATCH   4
#define SEQ     2048
#define TOK     (BATCH * SEQ)      // 8192
#define DMODEL  384
#define INNER   768
#define STATE   16
#define KW      4
#define FFN     1024

// scan chunking
#define CH      16                 // chunks per sequence
#define CT      (SEQ / CH)         // 128 steps per chunk

// ---------------------------------------------------------------------------
// Scratch (device globals; no allocation allowed)
// ---------------------------------------------------------------------------
__device__ float g_h   [TOK * DMODEL];        // rms1 out
__device__ float g_xz  [TOK * 2 * INNER];     // in_proj out (x_inner | z)
__device__ float g_xs  [TOK * KW * INNER];    // im2col shifted input for conv
__device__ float g_xc  [TOK * INNER];         // conv out (silu)
__device__ float g_bc  [TOK * 2 * STATE];     // x_proj out (B | C)
__device__ float g_dl  [TOK * INNER];         // dsp = softplus(delta)
__device__ float g_y   [TOK * INNER];         // gated scan output
__device__ float g_o   [TOK * DMODEL];        // out_proj result
__device__ float g_x2  [TOK * DMODEL];        // residual after mamba
__device__ float g_h2  [TOK * DMODEL];        // rms2 out
__device__ float g_gate[TOK * FFN];
__device__ float g_hid [TOK * FFN];
__device__ float g_pa  [BATCH * CH * INNER * STATE];  // chunk propagator
__device__ float g_he  [BATCH * CH * INNER * STATE];  // chunk end state (local)
__device__ float g_hin [BATCH * CH * INNER * STATE];  // state entering chunk

// ---------------------------------------------------------------------------
// TF32 tensor-core GEMM: C[M,N] = A[M,K] @ B[K,N], row-major.
// CTA tile 128x128, BK=16 double-buffered, 8 warps each 32(M)x64(N),
// mma.sync.aligned.m16n8k8.row.col.f32.tf32.tf32.f32
// Requirements: M % 128 == 0, K % 16 == 0, N % 4 == 0 (guards on N only).
// mode: 0 = store
//       1 = silu(acc+bias)
//       2 = acc+bias
//       3 = acc + res[m*N+n]
//       4 = softplus(acc+bias)
//       5 = silu(res[m*N+n]) * acc
// ---------------------------------------------------------------------------
#define BM 128
#define BN 128
#define BKT 16
#define LDA (BM + 4)
#define LDB (BN + 4)

__device__ __forceinline__ uint32_t f2tf(float f)
{
    uint32_t u;
    asm("cvt.rna.tf32.f32 %0, %1;" : "=r"(u) : "f"(f));
    return u;
}

__device__ __forceinline__ void mma_tf32(float c[4], const uint32_t a[4],
                                         const uint32_t b[2])
{
    asm volatile(
        "mma.sync.aligned.m16n8k8.row.col.f32.tf32.tf32.f32 "
        "{%0,%1,%2,%3}, {%4,%5,%6,%7}, {%8,%9}, {%0,%1,%2,%3};\n"
        : "+f"(c[0]), "+f"(c[1]), "+f"(c[2]), "+f"(c[3])
        : "r"(a[0]), "r"(a[1]), "r"(a[2]), "r"(a[3]),
          "r"(b[0]), "r"(b[1]));
}

__device__ __forceinline__ float epi_apply(float v, int mode, int n, int N,
                                           int m, const float* bias,
                                           const float* res)
{
    if (mode == 1) {
        v += bias[n];
        v = v / (1.f + __expf(-v));
    } else if (mode == 2) {
        v += bias[n];
    } else if (mode == 3) {
        v += res[(size_t)m * N + n];
    } else if (mode == 4) {
        v += bias[n];
        v = (v > 20.f) ? v : log1pf(__expf(v));
    } else if (mode == 5) {
        const float gv = res[(size_t)m * N + n];
        v *= gv / (1.f + __expf(-gv));
    }
    return v;
}

__global__ __launch_bounds__(256, 2) void mma_gemm_kernel(
    const float* __restrict__ A, const float* __restrict__ B,
    float* __restrict__ C, int M, int N, int K,
    int mode, const float* __restrict__ bias, const float* __restrict__ res)
{
    __shared__ uint32_t As[2][BKT][LDA];
    __shared__ uint32_t Bs[2][BKT][LDB];

    const int tid  = threadIdx.x;
    const int wid  = tid >> 5;
    const int lane = tid & 31;
    const int g    = lane >> 2;   // 0..7
    const int tig  = lane & 3;    // 0..3

    const int warpM = (wid & 3) * 32;
    const int warpN = (wid >> 2) * 64;

    const int m0 = blockIdx.y * BM;
    const int n0 = blockIdx.x * BN;

    const int ar = tid >> 2;          // 0..63  (rows ar, ar+64)
    const int ac = (tid & 3) * 4;     // 0,4,8,12
    const int br = tid >> 5;          // 0..7   (rows br, br+8)
    const int bcn = (tid & 31) * 4;   // 0..124

    float acc[2][8][4];
    #pragma unroll
    for (int mt = 0; mt < 2; mt++)
        #pragma unroll
        for (int nt = 0; nt < 8; nt++)
            #pragma unroll
            for (int r = 0; r < 4; r++) acc[mt][nt][r] = 0.f;

    const bool bok = (n0 + bcn + 3) < N;
    const float4 zero4 = make_float4(0.f, 0.f, 0.f, 0.f);

    const float* Ab = A + (size_t)(m0 + ar) * K + ac;
    const float* Bb = B + (size_t)br * N + n0 + bcn;

    float4 av0, av1, bv0, bv1;

    av0 = *(const float4*)(Ab);
    av1 = *(const float4*)(Ab + (size_t)64 * K);
    bv0 = bok ? *(const float4*)(Bb) : zero4;
    bv1 = bok ? *(const float4*)(Bb + (size_t)8 * N) : zero4;

    const int ntiles = K / BKT;
    int buf = 0;

    {
        As[0][ac + 0][ar] = f2tf(av0.x);
        As[0][ac + 1][ar] = f2tf(av0.y);
        As[0][ac + 2][ar] = f2tf(av0.z);
        As[0][ac + 3][ar] = f2tf(av0.w);
        As[0][ac + 0][ar + 64] = f2tf(av1.x);
        As[0][ac + 1][ar + 64] = f2tf(av1.y);
        As[0][ac + 2][ar + 64] = f2tf(av1.z);
        As[0][ac + 3][ar + 64] = f2tf(av1.w);
        Bs[0][br][bcn + 0] = f2tf(bv0.x);
        Bs[0][br][bcn + 1] = f2tf(bv0.y);
        Bs[0][br][bcn + 2] = f2tf(bv0.z);
        Bs[0][br][bcn + 3] = f2tf(bv0.w);
        Bs[0][br + 8][bcn + 0] = f2tf(bv1.x);
        Bs[0][br + 8][bcn + 1] = f2tf(bv1.y);
        Bs[0][br + 8][bcn + 2] = f2tf(bv1.z);
        Bs[0][br + 8][bcn + 3] = f2tf(bv1.w);
    }
    __syncthreads();

    for (int t = 0; t < ntiles; t++) {
        if (t + 1 < ntiles) {
            const int k0 = (t + 1) * BKT;
            av0 = *(const float4*)(Ab + k0);
            av1 = *(const float4*)(Ab + k0 + (size_t)64 * K);
            bv0 = bok ? *(const float4*)(Bb + (size_t)k0 * N) : zero4;
            bv1 = bok ? *(const float4*)(Bb + (size_t)(k0 + 8) * N) : zero4;
        }

        #pragma unroll
        for (int ks = 0; ks < BKT; ks += 8) {
            uint32_t afr[2][4];
            #pragma unroll
            for (int mt = 0; mt < 2; mt++) {
                const int mb = warpM + mt * 16;
                afr[mt][0] = As[buf][ks + tig    ][mb + g];
                afr[mt][1] = As[buf][ks + tig    ][mb + g + 8];
                afr[mt][2] = As[buf][ks + tig + 4][mb + g];
                afr[mt][3] = As[buf][ks + tig + 4][mb + g + 8];
            }
            uint32_t bfr[8][2];
            #pragma unroll
            for (int nt = 0; nt < 8; nt++) {
                const int nb = warpN + nt * 8;
                bfr[nt][0] = Bs[buf][ks + tig    ][nb + g];
                bfr[nt][1] = Bs[buf][ks + tig + 4][nb + g];
            }
            #pragma unroll
            for (int mt = 0; mt < 2; mt++)
                #pragma unroll
                for (int nt = 0; nt < 8; nt++)
                    mma_tf32(acc[mt][nt], afr[mt], bfr[nt]);
        }

        if (t + 1 < ntiles) {
            const int nb = buf ^ 1;
            As[nb][ac + 0][ar] = f2tf(av0.x);
            As[nb][ac + 1][ar] = f2tf(av0.y);
            As[nb][ac + 2][ar] = f2tf(av0.z);
            As[nb][ac + 3][ar] = f2tf(av0.w);
            As[nb][ac + 0][ar + 64] = f2tf(av1.x);
            As[nb][ac + 1][ar + 64] = f2tf(av1.y);
            As[nb][ac + 2][ar + 64] = f2tf(av1.z);
            As[nb][ac + 3][ar + 64] = f2tf(av1.w);
            Bs[nb][br][bcn + 0] = f2tf(bv0.x);
            Bs[nb][br][bcn + 1] = f2tf(bv0.y);
            Bs[nb][br][bcn + 2] = f2tf(bv0.z);
            Bs[nb][br][bcn + 3] = f2tf(bv0.w);
            Bs[nb][br + 8][bcn + 0] = f2tf(bv1.x);
            Bs[nb][br + 8][bcn + 1] = f2tf(bv1.y);
            Bs[nb][br + 8][bcn + 2] = f2tf(bv1.z);
            Bs[nb][br + 8][bcn + 3] = f2tf(bv1.w);
            __syncthreads();
            buf = nb;
        }
    }

    #pragma unroll
    for (int mt = 0; mt < 2; mt++) {
        #pragma unroll
        for (int nt = 0; nt < 8; nt++) {
            const int mA = m0 + warpM + mt * 16 + g;
            const int mB = mA + 8;
            const int n  = n0 + warpN + nt * 8 + tig * 2;
            #pragma unroll
            for (int half = 0; half < 2; half++) {
                const int m = half ? mB : mA;
                float v0 = half ? acc[mt][nt][2] : acc[mt][nt][0];
                float v1 = half ? acc[mt][nt][3] : acc[mt][nt][1];
                if (n < N) {
                    v0 = epi_apply(v0, mode, n, N, m, bias, res);
                    C[(size_t)m * N + n] = v0;
                }
                if (n + 1 < N) {
                    v1 = epi_apply(v1, mode, n + 1, N, m, bias, res);
                    C[(size_t)m * N + n + 1] = v1;
                }
            }
        }
    }
}

// ---------------------------------------------------------------------------
// RMSNorm (warp per token, D=384 -> 12 elems/lane)
// ---------------------------------------------------------------------------
__global__ void rmsnorm_kernel(const float* __restrict__ x,
                               const float* __restrict__ w,
                               float* __restrict__ out)
{
    const int warp = (blockIdx.x * blockDim.x + threadIdx.x) >> 5;
    const int lane = threadIdx.x & 31;
    if (warp >= TOK) return;
    const float* row = x + (size_t)warp * DMODEL;
    float ss = 0.f;
    float v[12];
    #pragma unroll
    for (int c = 0; c < 12; c++) {
        v[c] = row[lane + c * 32];
        ss += v[c] * v[c];
    }
    #pragma unroll
    for (int o = 16; o; o >>= 1) ss += __shfl_xor_sync(0xffffffffu, ss, o);
    const float inv = rsqrtf(ss * (1.f / DMODEL) + 1e-6f);
    float* orow = out + (size_t)warp * DMODEL;
    #pragma unroll
    for (int c = 0; c < 12; c++) {
        const int i = lane + c * 32;
        orow[i] = v[c] * inv * w[i];
    }
}

// ---------------------------------------------------------------------------
// im2col for conv: xs[tok, w*INNER + i] = x_inner[b, t-1+w, i] (0 outside seq)
// ---------------------------------------------------------------------------
__global__ void conv_shift_kernel(const float* __restrict__ xz,
                                  float* __restrict__ xs)
{
    const int idx = blockIdx.x * blockDim.x + threadIdx.x;   // float4 id
    const int total = TOK * KW * INNER / 4;
    if (idx >= total) return;
    const int e = idx * 4;
    const int tok = e / (KW * INNER);
    const int c = e - tok * (KW * INNER);
    const int w = c / INNER;
    const int i = c - w * INNER;
    const int b = tok >> 11;
    const int t = tok & (SEQ - 1);
    const int ts = t - 1 + w;
    float4 v = make_float4(0.f, 0.f, 0.f, 0.f);
    if (ts >= 0 && ts < SEQ)
        v = *(const float4*)(xz + ((size_t)(b * SEQ + ts)) * (2 * INNER) + i);
    *(float4*)(xs + (size_t)e) = v;
}

// ---------------------------------------------------------------------------
// Chunked selective scan.
// Phase 1: per (b, chunk, d, n): local scan with h_in = 0.
//   yloc[tok,d] = sum_n C*s  + D*x ;  pa = exp(A * sum dsp) ; he = s_end
// ---------------------------------------------------------------------------
__global__ void scan_chunk_kernel(const float* __restrict__ xc,
                                  const float* __restrict__ dsp_,
                                  const float* __restrict__ bc,
                                  const float* __restrict__ A_log,
                                  const float* __restrict__ Dp,
                                  float* __restrict__ yloc,
                                  float* __restrict__ pa,
                                  float* __restrict__ he)
{
    const int idx = blockIdx.x * blockDim.x + threadIdx.x;
    const int n = idx & 15;
    const int grp = idx >> 4;              // (b*CH + c)*INNER + d
    const int d = grp % INNER;
    const int bch = grp / INNER;           // b*CH + c
    const int c = bch & (CH - 1);
    const int b = bch >> 4;                // CH == 16

    const float A = -__expf(A_log[d * STATE + n]);
    const float Dv = Dp[d];
    float S = 0.f, s = 0.f;

    size_t tok = (size_t)b * SEQ + (size_t)c * CT;

    float dsp = dsp_[tok * INNER + d];
    float xv  = xc[tok * INNER + d];
    float Bv  = bc[tok * 2 * STATE + n];
    float Cv  = bc[tok * 2 * STATE + STATE + n];

    for (int t = 0; t < CT; t++) {
        float dsp_nx = 0.f, x_nx = 0.f, b_nx = 0.f, c_nx = 0.f;
        if (t + 1 < CT) {
            const size_t tk = tok + 1;
            dsp_nx = dsp_[tk * INNER + d];
            x_nx   = xc[tk * INNER + d];
            b_nx   = bc[tk * 2 * STATE + n];
            c_nx   = bc[tk * 2 * STATE + STATE + n];
        }
        S += dsp;
        const float a = __expf(A * dsp);
        s = a * s + dsp * Bv * xv;
        float p = Cv * s;
        p += __shfl_xor_sync(0xffffffffu, p, 8);
        p += __shfl_xor_sync(0xffffffffu, p, 4);
        p += __shfl_xor_sync(0xffffffffu, p, 2);
        p += __shfl_xor_sync(0xffffffffu, p, 1);
        if (n == 0)
            yloc[tok * INNER + d] = p + Dv * xv;
        tok++;
        dsp = dsp_nx; xv = x_nx; Bv = b_nx; Cv = c_nx;
    }

    const size_t o = (size_t)grp * STATE + n;
    pa[o] = __expf(A * S);
    he[o] = s;
}

// ---------------------------------------------------------------------------
// Phase 2: sequential combine over chunks. thread per (b, d, n).
// hin[chunk c] = state entering chunk c.
// ---------------------------------------------------------------------------
__global__ void scan_combine_kernel(const float* __restrict__ pa,
                                    const float* __restrict__ he,
                                    float* __restrict__ hin)
{
    const int idx = blockIdx.x * blockDim.x + threadIdx.x;
    if (idx >= BATCH * INNER * STATE) return;
    const int n = idx & 15;
    const int grp = idx >> 4;              // b*INNER + d
    const int d = grp % INNER;
    const int b = grp / INNER;

    float h = 0.f;
    #pragma unroll
    for (int c = 0; c < CH; c++) {
        const size_t o = (((size_t)(b * CH + c) * INNER) + d) * STATE + n;
        hin[o] = h;
        h = pa[o] * h + he[o];
    }
}

// ---------------------------------------------------------------------------
// Phase 3: add cross-chunk correction, apply silu(z) gate.
// y[tok,d] = (yloc + sum_n C_t[n] * exp(A[n]*S_t) * h_in[n]) * silu(z)
// ---------------------------------------------------------------------------
__global__ void scan_fixup_kernel(const float* __restrict__ dsp_,
                                  const float* __restrict__ bc,
                                  const float* __restrict__ A_log,
                                  const float* __restrict__ hin,
                                  const float* __restrict__ yloc,
                                  const float* __restrict__ xz,
                                  float* __restrict__ y)
{
    const int idx = blockIdx.x * blockDim.x + threadIdx.x;
    const int n = idx & 15;
    const int grp = idx >> 4;              // (b*CH + c)*INNER + d
    const int d = grp % INNER;
    const int bch = grp / INNER;
    const int c = bch & (CH - 1);
    const int b = bch >> 4;

    const float A = -__expf(A_log[d * STATE + n]);
    const float h0 = hin[(size_t)grp * STATE + n];
    float S = 0.f;

    size_t tok = (size_t)b * SEQ + (size_t)c * CT;

    float dsp = dsp_[tok * INNER + d];
    float Cv  = bc[tok * 2 * STATE + STATE + n];

    for (int t = 0; t < CT; t++) {
        float dsp_nx = 0.f, c_nx = 0.f;
        if (t + 1 < CT) {
            const size_t tk = tok + 1;
            dsp_nx = dsp_[tk * INNER + d];
            c_nx   = bc[tk * 2 * STATE + STATE + n];
        }
        S += dsp;
        float p = Cv * __expf(A * S) * h0;
        p += __shfl_xor_sync(0xffffffffu, p, 8);
        p += __shfl_xor_sync(0xffffffffu, p, 4);
        p += __shfl_xor_sync(0xffffffffu, p, 2);
        p += __shfl_xor_sync(0xffffffffu, p, 1);
        if (n == 0) {
            const float zv = xz[tok * 2 * INNER + INNER + d];
            const float sz = zv / (1.f + __expf(-zv));
            y[tok * INNER + d] = (yloc[tok * INNER + d] + p) * sz;
        }
        tok++;
        dsp = dsp_nx; Cv = c_nx;
    }
}

// ---------------------------------------------------------------------------
// Fused: x2 = xres + LayerNorm(o)*gamma+beta ; h2 = RMSNorm(x2)*rms_w
// ---------------------------------------------------------------------------
__global__ void ln_residual_rms_kernel(const float* __restrict__ o_,
                                       const float* __restrict__ xres,
                                       const float* __restrict__ gamma,
                                       const float* __restrict__ beta,
                                       const float* __restrict__ rms_w,
                                       float* __restrict__ x2,
                                       float* __restrict__ h2)
{
    const int warp = (blockIdx.x * blockDim.x + threadIdx.x) >> 5;
    const int lane = threadIdx.x & 31;
    if (warp >= TOK) return;
    const size_t row = (size_t)warp * DMODEL;

    float o[12];
    float mu = 0.f;
    #pragma unroll
    for (int c = 0; c < 12; c++) {
        o[c] = o_[row + lane + c * 32];
        mu += o[c];
    }
    #pragma unroll
    for (int s = 16; s; s >>= 1) mu += __shfl_xor_sync(0xffffffffu, mu, s);
    mu *= (1.f / DMODEL);

    float var = 0.f;
    #pragma unroll
    for (int c = 0; c < 12; c++) {
        const float dd = o[c] - mu;
        var += dd * dd;
    }
    #pragma unroll
    for (int s = 16; s; s >>= 1) var += __shfl_xor_sync(0xffffffffu, var, s);
    var *= (1.f / DMODEL);
    const float inv = rsqrtf(var + 1e-5f);

    float r[12];
    float ss = 0.f;
    #pragma unroll
    for (int c = 0; c < 12; c++) {
        const int i = lane + c * 32;
        const float v = xres[row + i] + (o[c] - mu) * inv * gamma[i] + beta[i];
        r[c] = v;
        x2[row + i] = v;
        ss += v * v;
    }
    #pragma unroll
    for (int s = 16; s; s >>= 1) ss += __shfl_xor_sync(0xffffffffu, ss, s);
    const float rinv = rsqrtf(ss * (1.f / DMODEL) + 1e-6f);
    #pragma unroll
    for (int c = 0; c < 12; c++) {
        const int i = lane + c * 32;
        h2[row + i] = r[c] * rinv * rms_w[i];
    }
}

// ---------------------------------------------------------------------------
// launch
// ---------------------------------------------------------------------------
static inline float* sym(const void* symbol)
{
    void* p = nullptr;
    cudaGetSymbolAddress(&p, symbol);
    return (float*)p;
}

extern "C" void kernel_launch(void* const* d_in, const int* in_sizes, int n_in,
                              void* d_out, int out_size)
{
    const float* x        = (const float*)d_in[0];
    const float* rms1_w   = (const float*)d_in[1];
    const float* rms2_w   = (const float*)d_in[2];
    const float* in_proj  = (const float*)d_in[3];
    const float* conv_w   = (const float*)d_in[4];
    const float* conv_b   = (const float*)d_in[5];
    const float* x_proj   = (const float*)d_in[6];
    const float* dt_proj  = (const float*)d_in[7];
    const float* dt_b     = (const float*)d_in[8];
    const float* A_log    = (const float*)d_in[9];
    const float* D_param  = (const float*)d_in[10];
    const float* out_proj = (const float*)d_in[11];
    const float* ln_g     = (const float*)d_in[12];
    const float* ln_b     = (const float*)d_in[13];
    const float* gate_w   = (const float*)d_in[14];
    const float* up_w     = (const float*)d_in[15];
    const float* down_w   = (const float*)d_in[16];
    float* out = (float*)d_out;

    float* h    = sym(g_h);
    float* xz   = sym(g_xz);
    float* xs   = sym(g_xs);
    float* xc   = sym(g_xc);
    float* bcp  = sym(g_bc);
    float* dl   = sym(g_dl);
    float* y    = sym(g_y);
    float* o    = sym(g_o);
    float* x2   = sym(g_x2);
    float* h2   = sym(g_h2);
    float* gate = sym(g_gate);
    float* hid  = sym(g_hid);
    float* pa   = sym(g_pa);
    float* he   = sym(g_he);
    float* hin  = sym(g_hin);

    const dim3 tpb(256);

    // 1. h = rmsnorm(x) * rms1_w
    rmsnorm_kernel<<<TOK / 8, 256>>>(x, rms1_w, h);

    // 2. xz = h @ in_proj_w   [8192,1536] K=384
    mma_gemm_kernel<<<dim3((2 * INNER) / BN, TOK / BM), tpb>>>(
        h, in_proj, xz, TOK, 2 * INNER, DMODEL, 0, nullptr, nullptr);

    // 3. im2col shift
    {
        const int total = TOK * KW * INNER / 4;
        conv_shift_kernel<<<(total + 255) / 256, tpb>>>(xz, xs);
    }

    // 4. xc = silu(xs @ conv_w_reshaped + conv_b)   K=3072
    mma_gemm_kernel<<<dim3(INNER / BN, TOK / BM), tpb>>>(
        xs, conv_w, xc, TOK, INNER, KW * INNER, 1, conv_b, nullptr);

    // 5. bc = xc @ x_proj_w   [8192,32]  K=768
    mma_gemm_kernel<<<dim3(1, TOK / BM), tpb>>>(
        xc, x_proj, bcp, TOK, 2 * STATE, INNER, 0, nullptr, nullptr);

    // 6. dsp = softplus(xc @ dt_proj_w + dt_b)   K=768
    mma_gemm_kernel<<<dim3(INNER / BN, TOK / BM), tpb>>>(
        xc, dt_proj, dl, TOK, INNER, INNER, 4, dt_b, nullptr);

    // 7. chunked selective scan + gating
    scan_chunk_kernel<<<(BATCH * CH * INNER * STATE) / 256, tpb>>>(
        xc, dl, bcp, A_log, D_param, y, pa, he);
    scan_combine_kernel<<<(BATCH * INNER * STATE + 255) / 256, tpb>>>(
        pa, he, hin);
    scan_fixup_kernel<<<(BATCH * CH * INNER * STATE) / 256, tpb>>>(
        dl, bcp, A_log, hin, y, xz, y);

    // 8. o = y @ out_proj_w   [8192,384] K=768
    mma_gemm_kernel<<<dim3(DMODEL / BN, TOK / BM), tpb>>>(
        y, out_proj, o, TOK, DMODEL, INNER, 0, nullptr, nullptr);

    // 9. x2 = x + LN(o); h2 = RMSNorm(x2)
    ln_residual_rms_kernel<<<TOK / 8, 256>>>(o, x, ln_g, ln_b, rms2_w, x2, h2);

    // 10. gate GEMM  K=384
    mma_gemm_kernel<<<dim3(FFN / BN, TOK / BM), tpb>>>(
        h2, gate_w, gate, TOK, FFN, DMODEL, 0, nullptr, nullptr);
    // 11. hid = silu(gate) * (h2 @ up_w)   (fused)
    mma_gemm_kernel<<<dim3(FFN / BN, TOK / BM), tpb>>>(
        h2, up_w, hid, TOK, FFN, DMODEL, 5, nullptr, gate);

    // 12. out = x2 + hid @ down_w   K=1024
    mma_gemm_kernel<<<dim3(DMODEL / BN, TOK / BM), tpb>>>(
        hid, down_w, out, TOK, DMODEL, FFN, 3, nullptr, x2);
}